// round 1
// baseline (speedup 1.0000x reference)
#include <cuda_runtime.h>

// FlexHNN fused kernel, fp32 SIMT baseline.
// Pipeline per 64-row tile (all in one kernel, one block per tile):
//   t1 = tanh(z @ hW1^T + hb1)                      -> sA
//   a2 = t1 @ hW2^T + hb2 ; s2 = 1 - tanh(a2)^2     (register epilogue)
//   f  = z @ fW1^T + fb1 ; g = .5*f*s2 + .5*tanh(f) -> sA
//   f2 = g @ fW2^T + fb2 ; s1 recomputed from z     (register epilogue)
//   h  = .5*f2*s1 + .5*tanh(f2)                     -> sA
//   o  = h @ fW3^T + fb3 ; dz = [o[:,8:], -o[:,:8]] -> out

#define DZv 16
#define Hv 256
#define BM 64
#define NTHREADS 256
#define KC 32
#define NC (Hv / KC)      // 8 K-chunks
#define WKS 33            // weight tile row stride (floats), bank-conflict-free
#define AS (Hv + 1)       // 257: activation row stride
#define ZS (DZv + 1)      // 17:  z / W1 row stride

__device__ __forceinline__ float fast_tanh(float x) {
    // tanh(x) = 1 - 2/(exp(2x)+1); safe at +-inf, ~1e-7 rel error via __expf
    float e = __expf(2.0f * x);
    return 1.0f - 2.0f / (e + 1.0f);
}

// acc[r][c] = sum_k sA[row0+r][k] * Wg[lane+32c][k]   (Wg row-major [256][256])
__device__ __forceinline__ void big_gemm(const float* __restrict__ Wg,
                                         const float* __restrict__ sA,
                                         float* __restrict__ sW,
                                         int tid, int lane, int row0,
                                         float (&acc)[8][8])
{
#pragma unroll
    for (int r = 0; r < 8; ++r)
#pragma unroll
        for (int c = 0; c < 8; ++c) acc[r][c] = 0.0f;

    float4 ld[8];
    // prefetch chunk 0: 256 rows x 32 k = 2048 float4, 8 per thread
#pragma unroll
    for (int i = 0; i < 8; ++i) {
        int idx = i * NTHREADS + tid;
        int j = idx >> 3, q = idx & 7;
        ld[i] = *(const float4*)(Wg + j * Hv + q * 4);
    }

    for (int ch = 0; ch < NC; ++ch) {
        // stage current chunk into sW[j*33 + k] (stores conflict-free: bank = j+4q+s)
#pragma unroll
        for (int i = 0; i < 8; ++i) {
            int idx = i * NTHREADS + tid;
            int j = idx >> 3, q = idx & 7;
            float* p = sW + j * WKS + q * 4;
            p[0] = ld[i].x; p[1] = ld[i].y; p[2] = ld[i].z; p[3] = ld[i].w;
        }
        __syncthreads();

        // prefetch next chunk (LDG latency hidden behind compute)
        if (ch + 1 < NC) {
            int k0n = (ch + 1) * KC;
#pragma unroll
            for (int i = 0; i < 8; ++i) {
                int idx = i * NTHREADS + tid;
                int j = idx >> 3, q = idx & 7;
                ld[i] = *(const float4*)(Wg + j * Hv + k0n + q * 4);
            }
        }

        const int k0 = ch * KC;
#pragma unroll 4
        for (int kk = 0; kk < KC; ++kk) {
            float a[8], b[8];
#pragma unroll
            for (int r = 0; r < 8; ++r)          // broadcast within warp
                a[r] = sA[(row0 + r) * AS + k0 + kk];
#pragma unroll
            for (int c = 0; c < 8; ++c)          // bank = (lane+kk)%32, conflict-free
                b[c] = sW[(lane + 32 * c) * WKS + kk];
#pragma unroll
            for (int r = 0; r < 8; ++r)
#pragma unroll
                for (int c = 0; c < 8; ++c)
                    acc[r][c] = fmaf(a[r], b[c], acc[r][c]);
        }
        __syncthreads();
    }
}

__global__ void __launch_bounds__(NTHREADS, 1)
flexhnn_kernel(const float* __restrict__ z,
               const float* __restrict__ hW1, const float* __restrict__ hb1,
               const float* __restrict__ hW2, const float* __restrict__ hb2,
               const float* __restrict__ fW1, const float* __restrict__ fb1,
               const float* __restrict__ fW2, const float* __restrict__ fb2,
               const float* __restrict__ fW3, const float* __restrict__ fb3,
               float* __restrict__ out)
{
    extern __shared__ float sm[];
    float* sA   = sm;                       // BM*AS       activations
    float* sW   = sA   + BM * AS;           // Hv*WKS      weight K-chunk
    float* sZ   = sW   + Hv * WKS;          // BM*ZS       z tile
    float* sHW1 = sZ   + BM * ZS;           // Hv*ZS
    float* sFW1 = sHW1 + Hv * ZS;           // Hv*ZS
    float* sFW3 = sFW1 + Hv * ZS;           // DZv*AS
    float* sHB1 = sFW3 + DZv * AS;          // Hv
    float* sHB2 = sHB1 + Hv;
    float* sFB1 = sHB2 + Hv;
    float* sFB2 = sFB1 + Hv;
    float* sFB3 = sFB2 + Hv;                // DZv

    const int tid  = threadIdx.x;
    const int lane = tid & 31;
    const int wrp  = tid >> 5;
    const int row0 = wrp * 8;
    const long n0  = (long)blockIdx.x * BM;

    // ---- cooperative load of small weights / biases / z tile ----
    for (int i = tid; i < Hv * DZv; i += NTHREADS) {
        int j = i >> 4, d = i & 15;
        sHW1[j * ZS + d] = hW1[i];
        sFW1[j * ZS + d] = fW1[i];
    }
    for (int i = tid; i < DZv * Hv; i += NTHREADS) {
        int j = i >> 8, k = i & 255;
        sFW3[j * AS + k] = fW3[i];
    }
    {
        sHB1[tid] = hb1[tid]; sHB2[tid] = hb2[tid];
        sFB1[tid] = fb1[tid]; sFB2[tid] = fb2[tid];
        if (tid < DZv) sFB3[tid] = fb3[tid];
    }
    {
        float4 v = ((const float4*)(z + n0 * DZv))[tid];   // 64*16 floats = 256 float4
        int r = tid >> 2, c = (tid & 3) * 4;
        sZ[r * ZS + c + 0] = v.x; sZ[r * ZS + c + 1] = v.y;
        sZ[r * ZS + c + 2] = v.z; sZ[r * ZS + c + 3] = v.w;
    }
    __syncthreads();

    // ---- stage 1: t1 = tanh(z @ hW1^T + hb1) -> sA ----
#pragma unroll
    for (int r = 0; r < 8; ++r) {
        const int row = row0 + r;
        float zr[DZv];
#pragma unroll
        for (int d = 0; d < DZv; ++d) zr[d] = sZ[row * ZS + d];
#pragma unroll
        for (int c = 0; c < 8; ++c) {
            const int j = lane + 32 * c;
            float a = sHB1[j];
#pragma unroll
            for (int d = 0; d < DZv; ++d) a = fmaf(zr[d], sHW1[j * ZS + d], a);
            sA[row * AS + j] = fast_tanh(a);
        }
    }
    __syncthreads();

    float acc[8][8];

    // ---- GEMM2: a2 = t1 @ hW2^T ; epilogue -> g in sA ----
    big_gemm(hW2, sA, sW, tid, lane, row0, acc);
#pragma unroll
    for (int r = 0; r < 8; ++r) {
        const int row = row0 + r;
        float zr[DZv];
#pragma unroll
        for (int d = 0; d < DZv; ++d) zr[d] = sZ[row * ZS + d];
#pragma unroll
        for (int c = 0; c < 8; ++c) {
            const int j = lane + 32 * c;
            float t2 = fast_tanh(acc[r][c] + sHB2[j]);
            float s2 = 1.0f - t2 * t2;
            float f = sFB1[j];
#pragma unroll
            for (int d = 0; d < DZv; ++d) f = fmaf(zr[d], sFW1[j * ZS + d], f);
            sA[row * AS + j] = 0.5f * (f * s2) + 0.5f * fast_tanh(f);
        }
    }
    __syncthreads();

    // ---- GEMM3: f2 = g @ fW2^T ; epilogue (s1 recomputed from z) -> h in sA ----
    big_gemm(fW2, sA, sW, tid, lane, row0, acc);
#pragma unroll
    for (int r = 0; r < 8; ++r) {
        const int row = row0 + r;
        float zr[DZv];
#pragma unroll
        for (int d = 0; d < DZv; ++d) zr[d] = sZ[row * ZS + d];
#pragma unroll
        for (int c = 0; c < 8; ++c) {
            const int j = lane + 32 * c;
            float a1 = sHB1[j];
#pragma unroll
            for (int d = 0; d < DZv; ++d) a1 = fmaf(zr[d], sHW1[j * ZS + d], a1);
            float t1v = fast_tanh(a1);
            float s1 = 1.0f - t1v * t1v;
            float f2 = acc[r][c] + sFB2[j];
            sA[row * AS + j] = 0.5f * (f2 * s1) + 0.5f * fast_tanh(f2);
        }
    }
    __syncthreads();

    // ---- GEMM4: o = h @ fW3^T + fb3 ; symplectic swap -> out ----
    {
        const int j16  = lane & 15;
        const int rsub = (lane >> 4) * 4;
        const float* wrow = sFW3 + j16 * AS;
        const float* a0 = sA + (row0 + rsub + 0) * AS;
        const float* a1 = sA + (row0 + rsub + 1) * AS;
        const float* a2 = sA + (row0 + rsub + 2) * AS;
        const float* a3 = sA + (row0 + rsub + 3) * AS;
        float b = sFB3[j16];
        float o0 = b, o1 = b, o2 = b, o3 = b;
#pragma unroll 8
        for (int k = 0; k < Hv; ++k) {
            float w = wrow[k];
            o0 = fmaf(a0[k], w, o0);
            o1 = fmaf(a1[k], w, o1);
            o2 = fmaf(a2[k], w, o2);
            o3 = fmaf(a3[k], w, o3);
        }
        // dz[:, :8] = o[:, 8:] ; dz[:, 8:] = -o[:, :8]
        const int dst = (j16 + 8) & 15;
        const float sgn = (j16 < 8) ? -1.0f : 1.0f;
        const long base = (n0 + row0 + rsub) * DZv;
        out[base + 0 * DZv + dst] = sgn * o0;
        out[base + 1 * DZv + dst] = sgn * o1;
        out[base + 2 * DZv + dst] = sgn * o2;
        out[base + 3 * DZv + dst] = sgn * o3;
    }
}

extern "C" void kernel_launch(void* const* d_in, const int* in_sizes, int n_in,
                              void* d_out, int out_size)
{
    // metadata order: t, z, hW1, hb1, hW2, hb2, fW1, fb1, fW2, fb2, fW3, fb3
    const float* z   = (const float*)d_in[1];
    const float* hW1 = (const float*)d_in[2];
    const float* hb1 = (const float*)d_in[3];
    const float* hW2 = (const float*)d_in[4];
    const float* hb2 = (const float*)d_in[5];
    const float* fW1 = (const float*)d_in[6];
    const float* fb1 = (const float*)d_in[7];
    const float* fW2 = (const float*)d_in[8];
    const float* fb2 = (const float*)d_in[9];
    const float* fW3 = (const float*)d_in[10];
    const float* fb3 = (const float*)d_in[11];
    float* out = (float*)d_out;

    const int n = in_sizes[1] / DZv;     // 131072 rows
    const int grid = n / BM;             // 2048 blocks

    const int smem_bytes =
        (BM * AS + Hv * WKS + BM * ZS + 2 * Hv * ZS + DZv * AS + 4 * Hv + DZv)
        * (int)sizeof(float);            // ~159.4 KB

    cudaFuncSetAttribute(flexhnn_kernel,
                         cudaFuncAttributeMaxDynamicSharedMemorySize, smem_bytes);

    flexhnn_kernel<<<grid, NTHREADS, smem_bytes>>>(
        z, hW1, hb1, hW2, hb2, fW1, fb1, fW2, fb2, fW3, fb3, out);
}